// round 3
// baseline (speedup 1.0000x reference)
#include <cuda_runtime.h>
#include <math.h>

#define Bb   4
#define Ls   1024
#define Hh   768
#define NHh  12
#define NEe  30
#define Mm   6
#define Pp   600
#define EMBe 768
#define NCc  97
#define K2H  1536           // 2*H
#define QQ   12288          // EMB*BS
#define BP   (Bb*Pp)        // 2400

typedef unsigned long long u64;

__device__ __forceinline__ u64 ffma2(u64 a, u64 b, u64 c) {
    u64 d; asm("fma.rn.f32x2 %0,%1,%2,%3;" : "=l"(d) : "l"(a), "l"(b), "l"(c)); return d;
}
__device__ __forceinline__ u64 fmul2(u64 a, u64 b) {
    u64 d; asm("mul.rn.f32x2 %0,%1,%2;" : "=l"(d) : "l"(a), "l"(b)); return d;
}
__device__ __forceinline__ float lo32(u64 v) { return __uint_as_float((unsigned)v); }
__device__ __forceinline__ float hi32(u64 v) { return __uint_as_float((unsigned)(v >> 32)); }
__device__ __forceinline__ u64 dup2(float x) {
    unsigned b = __float_as_uint(x); return ((u64)b << 32) | (u64)b;
}

// ---------------- scratch ----------------
__device__ float g_e_emb[Bb*NEe*Hh];
__device__ float g_e_att[Bb*NEe*NHh*Ls];
__device__ float g_ht  [Bb*Pp*Ls];
__device__ float g_rs  [Bb*Pp*Hh];
__device__ float g_hs  [BP*EMBe];
__device__ float g_ts  [BP*EMBe];
__device__ float g_Wc  [NCc*QQ];

// ---------------- kernel 1: entity pooling ----------------
__global__ void pool_kernel(const float* __restrict__ seq,
                            const float* __restrict__ att,
                            const float* __restrict__ mmask,
                            const int*   __restrict__ midx)
{
    int be = blockIdx.x;
    int b = be / NEe;
    __shared__ int   idx[Mm];
    __shared__ float msk[Mm];
    if (threadIdx.x < Mm) {
        idx[threadIdx.x] = midx[be*Mm + threadIdx.x];
        msk[threadIdx.x] = mmask[be*Mm + threadIdx.x];
    }
    __syncthreads();
    float cnt = 0.f;
    #pragma unroll
    for (int m = 0; m < Mm; m++) cnt += msk[m];
    cnt = fmaxf(cnt, 1.0f);
    float invc = 1.0f / cnt;

    for (int h = threadIdx.x; h < Hh; h += blockDim.x) {
        float v[Mm]; float mx = -1e30f;
        #pragma unroll
        for (int m = 0; m < Mm; m++) {
            float x = seq[((long)b*Ls + idx[m])*Hh + h];
            x = (msk[m] > 0.f) ? x : -1e30f;
            v[m] = x; mx = fmaxf(mx, x);
        }
        float s = 0.f;
        #pragma unroll
        for (int m = 0; m < Mm; m++) s += expf(v[m] - mx);
        g_e_emb[(long)be*Hh + h] = mx + logf(s);
    }
    for (int t = threadIdx.x; t < NHh*Ls; t += blockDim.x) {
        int nh = t >> 10, l = t & (Ls-1);
        float s = 0.f;
        #pragma unroll
        for (int m = 0; m < Mm; m++)
            s += att[(((long)b*NHh + nh)*Ls + idx[m])*Ls + l] * msk[m];
        g_e_att[((long)be*NHh + nh)*Ls + l] = s * invc;
    }
}

// ---------------- kernel 2: pairwise attention mix ----------------
__global__ void htatt_kernel(const int* __restrict__ hts)
{
    int bp = blockIdx.x;
    int b = bp / Pp;
    int he = hts[bp*2 + 0];
    int te = hts[bp*2 + 1];
    const float* ha = &g_e_att[((long)(b*NEe + he))*NHh*Ls];
    const float* ta = &g_e_att[((long)(b*NEe + te))*NHh*Ls];
    __shared__ float sv[Ls];
    __shared__ float red[256];
    float lsum = 0.f;
    for (int l = threadIdx.x; l < Ls; l += blockDim.x) {
        float s = 0.f;
        #pragma unroll
        for (int nh = 0; nh < NHh; nh++)
            s += ha[nh*Ls + l] * ta[nh*Ls + l];
        s *= (1.0f / NHh);
        sv[l] = s; lsum += s;
    }
    red[threadIdx.x] = lsum;
    for (int o = 128; o > 0; o >>= 1) {
        __syncthreads();
        if (threadIdx.x < o) red[threadIdx.x] += red[threadIdx.x + o];
    }
    __syncthreads();
    float inv = 1.0f / (red[0] + 1e-30f);
    for (int l = threadIdx.x; l < Ls; l += blockDim.x)
        g_ht[(long)bp*Ls + l] = sv[l] * inv;
}

// ---------------- FFMA2 NN GEMM: C = A @ B ----------------
// Tile 64(M) x 128(N), 256 threads, micro 4m x 8n (pairs along N).
// A stored duplicated in smem ({a,a} per value); B stored normally.
// Requires N % 128 == 0, K % 16 == 0. M masked.
__global__ __launch_bounds__(256) void gemm_nn2(
    const float* __restrict__ A, const float* __restrict__ B, float* __restrict__ C,
    int M, int N, int K, long sA, long sB, long sC)
{
    __shared__ float As2[16][128];
    __shared__ float Bs [16][128];
    int bz = blockIdx.z;
    const float* Ab = A + (long)bz*sA;
    const float* Bp = B + (long)bz*sB;
    float*       Cb = C + (long)bz*sC;
    int m0 = blockIdx.x*64, n0 = blockIdx.y*128;
    int tid = threadIdx.x;

    int ar = tid >> 2;              // 0..63 (m row)
    int ak = (tid & 3) * 4;         // 0,4,8,12
    int am = m0 + ar; if (am > M-1) am = M-1;
    int bk = tid >> 5;              // 0..7
    int bn = (tid & 31) * 4;        // 0..124
    const float* aptr = Ab + (long)am*K + ak;
    const float* bptr = Bp + (long)bk*N + n0 + bn;

    float4 arg = *(const float4*)aptr;
    float4 br0 = *(const float4*)bptr;
    float4 br1 = *(const float4*)(bptr + (long)8*N);

    int tm = tid & 15, tn = tid >> 4;
    u64 acc[4][4];
    #pragma unroll
    for (int i = 0; i < 4; i++)
        #pragma unroll
        for (int j = 0; j < 4; j++) acc[i][j] = 0ULL;

    for (int k0 = 0; k0 < K; k0 += 16) {
        *(u64*)&As2[ak+0][2*ar] = dup2(arg.x);
        *(u64*)&As2[ak+1][2*ar] = dup2(arg.y);
        *(u64*)&As2[ak+2][2*ar] = dup2(arg.z);
        *(u64*)&As2[ak+3][2*ar] = dup2(arg.w);
        *(float4*)&Bs[bk  ][bn] = br0;
        *(float4*)&Bs[bk+8][bn] = br1;
        __syncthreads();
        if (k0 + 16 < K) {
            aptr += 16; bptr += (long)16*N;
            arg = *(const float4*)aptr;
            br0 = *(const float4*)bptr;
            br1 = *(const float4*)(bptr + (long)8*N);
        }
        #pragma unroll
        for (int kk = 0; kk < 16; kk++) {
            ulonglong2 a01 = *(const ulonglong2*)&As2[kk][tm*8];
            ulonglong2 a23 = *(const ulonglong2*)&As2[kk][tm*8+4];
            ulonglong2 b01 = *(const ulonglong2*)&Bs [kk][tn*8];
            ulonglong2 b23 = *(const ulonglong2*)&Bs [kk][tn*8+4];
            u64 av[4] = {a01.x, a01.y, a23.x, a23.y};
            u64 bv[4] = {b01.x, b01.y, b23.x, b23.y};
            #pragma unroll
            for (int i = 0; i < 4; i++)
                #pragma unroll
                for (int j = 0; j < 4; j++)
                    acc[i][j] = ffma2(av[i], bv[j], acc[i][j]);
        }
        __syncthreads();
    }
    #pragma unroll
    for (int i = 0; i < 4; i++) {
        int m = m0 + tm*4 + i;
        if (m >= M) continue;
        float4 o0 = make_float4(lo32(acc[i][0]), hi32(acc[i][0]),
                                lo32(acc[i][1]), hi32(acc[i][1]));
        float4 o1 = make_float4(lo32(acc[i][2]), hi32(acc[i][2]),
                                lo32(acc[i][3]), hi32(acc[i][3]));
        *(float4*)&Cb[(long)m*N + n0 + tn*8    ] = o0;
        *(float4*)&Cb[(long)m*N + n0 + tn*8 + 4] = o1;
    }
}

// ---------------- extractor GEMM (gathered A, W^T, tanh) ----------------
// out[b,p,e] = tanh( bias[e] + sum_k X[p,k] W[e,k] ), X = [e_emb[ent] | rs]
__global__ __launch_bounds__(256) void extract2(
    const float* __restrict__ headW, const float* __restrict__ headb,
    const float* __restrict__ tailW, const float* __restrict__ tailb,
    const int*   __restrict__ hts)
{
    __shared__ float As2[16][128];
    __shared__ float Bs [16][128];
    int z = blockIdx.z;
    int b = z >> 1, side = z & 1;
    const float* W    = side ? tailW : headW;
    const float* bias = side ? tailb : headb;
    float*       out  = side ? g_ts  : g_hs;
    int m0 = blockIdx.x*64, n0 = blockIdx.y*128;
    int tid = threadIdx.x;

    // A-fill: thread owns one p row
    int ar = tid >> 2;
    int ak = (tid & 3) * 4;
    int p  = m0 + ar; int pc = (p < Pp) ? p : (Pp-1);
    int ent = hts[((b*Pp + pc)*2) + side];
    const float* embrow = g_e_emb + (long)(b*NEe + ent)*Hh;
    const float* rsrow  = g_rs   + (long)(b*Pp  + pc)*Hh;

    // B-fill (transposed from W): thread owns 8 consecutive k of one e row
    int be_ = tid >> 1;               // 0..127 (e)
    int bkq = (tid & 1) * 8;          // 0 or 8
    const float* wptr = W + (long)(n0 + be_)*K2H + bkq;

    int k = ak;
    float4 arg = (k < Hh) ? *(const float4*)(embrow + k)
                          : *(const float4*)(rsrow + k - Hh);
    float4 wr0 = *(const float4*)wptr;
    float4 wr1 = *(const float4*)(wptr + 4);

    int tm = tid & 15, tn = tid >> 4;
    u64 acc[4][4];
    #pragma unroll
    for (int i = 0; i < 4; i++)
        #pragma unroll
        for (int j = 0; j < 4; j++) acc[i][j] = 0ULL;

    for (int k0 = 0; k0 < K2H; k0 += 16) {
        *(u64*)&As2[ak+0][2*ar] = dup2(arg.x);
        *(u64*)&As2[ak+1][2*ar] = dup2(arg.y);
        *(u64*)&As2[ak+2][2*ar] = dup2(arg.z);
        *(u64*)&As2[ak+3][2*ar] = dup2(arg.w);
        Bs[bkq+0][be_] = wr0.x; Bs[bkq+1][be_] = wr0.y;
        Bs[bkq+2][be_] = wr0.z; Bs[bkq+3][be_] = wr0.w;
        Bs[bkq+4][be_] = wr1.x; Bs[bkq+5][be_] = wr1.y;
        Bs[bkq+6][be_] = wr1.z; Bs[bkq+7][be_] = wr1.w;
        __syncthreads();
        if (k0 + 16 < K2H) {
            int kn = k0 + 16 + ak;
            arg = (kn < Hh) ? *(const float4*)(embrow + kn)
                            : *(const float4*)(rsrow + kn - Hh);
            wptr += 16;
            wr0 = *(const float4*)wptr;
            wr1 = *(const float4*)(wptr + 4);
        }
        #pragma unroll
        for (int kk = 0; kk < 16; kk++) {
            ulonglong2 a01 = *(const ulonglong2*)&As2[kk][tm*8];
            ulonglong2 a23 = *(const ulonglong2*)&As2[kk][tm*8+4];
            ulonglong2 b01 = *(const ulonglong2*)&Bs [kk][tn*8];
            ulonglong2 b23 = *(const ulonglong2*)&Bs [kk][tn*8+4];
            u64 av[4] = {a01.x, a01.y, a23.x, a23.y};
            u64 bv[4] = {b01.x, b01.y, b23.x, b23.y};
            #pragma unroll
            for (int i = 0; i < 4; i++)
                #pragma unroll
                for (int j = 0; j < 4; j++)
                    acc[i][j] = ffma2(av[i], bv[j], acc[i][j]);
        }
        __syncthreads();
    }
    float4 bi0 = *(const float4*)&bias[n0 + tn*8];
    float4 bi1 = *(const float4*)&bias[n0 + tn*8 + 4];
    #pragma unroll
    for (int i = 0; i < 4; i++) {
        int m = m0 + tm*4 + i;
        if (m >= Pp) continue;
        float* orow = out + (long)(b*Pp + m)*EMBe + n0 + tn*8;
        float4 o0 = make_float4(tanhf(lo32(acc[i][0]) + bi0.x), tanhf(hi32(acc[i][0]) + bi0.y),
                                tanhf(lo32(acc[i][1]) + bi0.z), tanhf(hi32(acc[i][1]) + bi0.w));
        float4 o1 = make_float4(tanhf(lo32(acc[i][2]) + bi1.x), tanhf(hi32(acc[i][2]) + bi1.y),
                                tanhf(lo32(acc[i][3]) + bi1.z), tanhf(hi32(acc[i][3]) + bi1.w));
        *(float4*)(orow)     = o0;
        *(float4*)(orow + 4) = o1;
    }
}

// ---------------- block-bilinear classifier (FFMA2, m-axis pairing) -----------
// out[m,c] = cls_b[c] + sum_{k,i,j} hs[m,16k+i] ts[m,16k+j] Wc[c,256k+16i+j]
// Tile 64 m x 32 c, 256 threads, micro 2 m-pairs x 2 c. i split in halves of 8.
__global__ __launch_bounds__(256) void bilinear2(const float* __restrict__ clsb,
                                                 float* __restrict__ out)
{
    __shared__ float hs2_s[8][64];    // [i_local][m]  (m contiguous -> natural m-pairs)
    __shared__ float ts2_s[16][64];   // [j][m]
    __shared__ float Ws2 [128][64];   // [q'][2c duplicated]
    int m0 = blockIdx.x * 64;
    int c0 = blockIdx.y * 32;
    int tid = threadIdx.x;
    int tmp = tid & 15;               // m = m0 + 4*tmp + {0..3}
    int tcp = tid >> 4;               // c = c0 + 2*tcp + {0,1}

    // fill-thread index precompute
    int tsm = tid >> 2;               // 0..63
    int tsj = (tid & 3) * 4;          // 0,4,8,12
    int tsmg = m0 + tsm; if (tsmg >= BP) tsmg = BP - 1;
    int hm = tid & 63;
    int hi2 = (tid >> 6) * 2;         // 0,2,4,6
    int hmg = m0 + hm; if (hmg >= BP) hmg = BP - 1;
    int wc = tid >> 3;                // 0..31
    int wq = (tid & 7) * 16;          // 0..112
    int wcg = c0 + wc;
    bool wcv = (wcg < NCc);
    const float* wbase = g_Wc + (long)(wcv ? wcg : 0)*QQ;

    u64 acc[2][2] = {{0ULL,0ULL},{0ULL,0ULL}};   // [m-pair][c]

    for (int kb = 0; kb < EMBe/16; kb++) {
        #pragma unroll
        for (int ih = 0; ih < 2; ih++) {
            if (ih == 0) {
                float4 tv = *(const float4*)&g_ts[(long)tsmg*EMBe + kb*16 + tsj];
                ts2_s[tsj+0][tsm] = tv.x; ts2_s[tsj+1][tsm] = tv.y;
                ts2_s[tsj+2][tsm] = tv.z; ts2_s[tsj+3][tsm] = tv.w;
            }
            {
                float2 hv = *(const float2*)&g_hs[(long)hmg*EMBe + kb*16 + ih*8 + hi2];
                hs2_s[hi2  ][hm] = hv.x;
                hs2_s[hi2+1][hm] = hv.y;
            }
            {
                const float* wrow = wbase + kb*256 + ih*128 + wq;
                #pragma unroll
                for (int u = 0; u < 4; u++) {
                    float4 w = wcv ? *(const float4*)(wrow + u*4)
                                   : make_float4(0.f,0.f,0.f,0.f);
                    *(u64*)&Ws2[wq+u*4+0][2*wc] = dup2(w.x);
                    *(u64*)&Ws2[wq+u*4+1][2*wc] = dup2(w.y);
                    *(u64*)&Ws2[wq+u*4+2][2*wc] = dup2(w.z);
                    *(u64*)&Ws2[wq+u*4+3][2*wc] = dup2(w.w);
                }
            }
            __syncthreads();
            #pragma unroll
            for (int il = 0; il < 8; il++) {
                ulonglong2 h2 = *(const ulonglong2*)&hs2_s[il][tmp*4];
                #pragma unroll
                for (int j = 0; j < 16; j++) {
                    ulonglong2 t2 = *(const ulonglong2*)&ts2_s[j][tmp*4];
                    ulonglong2 w2 = *(const ulonglong2*)&Ws2[il*16 + j][tcp*4];
                    u64 pv0 = fmul2(h2.x, t2.x);
                    u64 pv1 = fmul2(h2.y, t2.y);
                    acc[0][0] = ffma2(pv0, w2.x, acc[0][0]);
                    acc[0][1] = ffma2(pv0, w2.y, acc[0][1]);
                    acc[1][0] = ffma2(pv1, w2.x, acc[1][0]);
                    acc[1][1] = ffma2(pv1, w2.y, acc[1][1]);
                }
            }
            __syncthreads();
        }
    }
    #pragma unroll
    for (int jc = 0; jc < 2; jc++) {
        int c = c0 + 2*tcp + jc;
        if (c >= NCc) continue;
        float bv = clsb[c];
        #pragma unroll
        for (int mp = 0; mp < 2; mp++) {
            int mbase = m0 + tmp*4 + mp*2;
            if (mbase < BP)     out[(long)mbase*NCc + c]     = lo32(acc[mp][jc]) + bv;
            if (mbase+1 < BP)   out[(long)(mbase+1)*NCc + c] = hi32(acc[mp][jc]) + bv;
        }
    }
}

// ---------------- launch ----------------
extern "C" void kernel_launch(void* const* d_in, const int* in_sizes, int n_in,
                              void* d_out, int out_size)
{
    const float* seq   = (const float*)d_in[0];
    const float* att   = (const float*)d_in[1];
    const float* headW = (const float*)d_in[2];
    const float* headb = (const float*)d_in[3];
    const float* tailW = (const float*)d_in[4];
    const float* tailb = (const float*)d_in[5];
    const float* projW = (const float*)d_in[6];
    const float* clsW  = (const float*)d_in[7];
    const float* clsb  = (const float*)d_in[8];
    const float* mmask = (const float*)d_in[9];
    const int*   midx  = (const int*)d_in[10];
    const int*   hts   = (const int*)d_in[11];
    float* out = (float*)d_out;

    float *p_ht, *p_rs, *p_Wc;
    cudaGetSymbolAddress((void**)&p_ht, g_ht);
    cudaGetSymbolAddress((void**)&p_rs, g_rs);
    cudaGetSymbolAddress((void**)&p_Wc, g_Wc);

    // Wc = cls_W @ proj_W   [97,768]@[768,12288]
    {
        dim3 g((NCc + 63)/64, QQ/128, 1);
        gemm_nn2<<<g, 256>>>(clsW, projW, p_Wc, NCc, QQ, Hh, 0, 0, 0);
    }
    pool_kernel<<<Bb*NEe, 256>>>(seq, att, mmask, midx);
    htatt_kernel<<<Bb*Pp, 256>>>(hts);
    // rs[b] = ht[b] @ seq[b]  (600x1024)@(1024x768)
    {
        dim3 g((Pp + 63)/64, Hh/128, Bb);
        gemm_nn2<<<g, 256>>>(p_ht, seq, p_rs, Pp, Hh, Ls,
                             (long)Pp*Ls, (long)Ls*Hh, (long)Pp*Hh);
    }
    // extractors
    {
        dim3 g((Pp + 63)/64, EMBe/128, Bb*2);
        extract2<<<g, 256>>>(headW, headb, tailW, tailb, hts);
    }
    // classifier
    {
        dim3 g((BP + 63)/64, (NCc + 31)/32, 1);
        bilinear2<<<g, 256>>>(clsb, out);
    }
}

// round 4
// speedup vs baseline: 1.7320x; 1.7320x over previous
#include <cuda_runtime.h>
#include <math.h>

#define Bb   4
#define Ls   1024
#define Hh   768
#define NHh  12
#define NEe  30
#define Mm   6
#define Pp   600
#define EMBe 768
#define NCc  97
#define K2H  1536           // 2*H
#define QQ   12288          // EMB*BS
#define BP   (Bb*Pp)        // 2400
#define BE   (Bb*NEe)       // 120
#define EKC  3              // K-chunks for E gemm (256 each)

// ---------------- scratch ----------------
__device__ float g_e_emb[BE*Hh];
__device__ float g_e_att[BE*NHh*Ls];
__device__ float g_ht  [BP*Ls];
__device__ float g_rs  [BP*Hh];
__device__ float g_R   [2*BP*Hh];          // [side][m][e]  rs @ W2^T
__device__ float g_Ep  [EKC*2*BE*Hh];      // partial e_emb @ W1^T
__device__ float g_hs  [BP*EMBe];
__device__ float g_ts  [BP*EMBe];
__device__ float g_Wc  [NCc*QQ];

// ---------------- kernel 1: entity pooling ----------------
__global__ void pool_kernel(const float* __restrict__ seq,
                            const float* __restrict__ att,
                            const float* __restrict__ mmask,
                            const int*   __restrict__ midx)
{
    int be = blockIdx.x;
    int b = be / NEe;
    __shared__ int   idx[Mm];
    __shared__ float msk[Mm];
    if (threadIdx.x < Mm) {
        idx[threadIdx.x] = midx[be*Mm + threadIdx.x];
        msk[threadIdx.x] = mmask[be*Mm + threadIdx.x];
    }
    __syncthreads();
    float cnt = 0.f;
    #pragma unroll
    for (int m = 0; m < Mm; m++) cnt += msk[m];
    cnt = fmaxf(cnt, 1.0f);
    float invc = 1.0f / cnt;

    for (int h = threadIdx.x; h < Hh; h += blockDim.x) {
        float v[Mm]; float mx = -1e30f;
        #pragma unroll
        for (int m = 0; m < Mm; m++) {
            float x = seq[((long)b*Ls + idx[m])*Hh + h];
            x = (msk[m] > 0.f) ? x : -1e30f;
            v[m] = x; mx = fmaxf(mx, x);
        }
        float s = 0.f;
        #pragma unroll
        for (int m = 0; m < Mm; m++) s += expf(v[m] - mx);
        g_e_emb[(long)be*Hh + h] = mx + logf(s);
    }
    for (int t = threadIdx.x; t < NHh*Ls; t += blockDim.x) {
        int nh = t >> 10, l = t & (Ls-1);
        float s = 0.f;
        #pragma unroll
        for (int m = 0; m < Mm; m++)
            s += att[(((long)b*NHh + nh)*Ls + idx[m])*Ls + l] * msk[m];
        g_e_att[((long)be*NHh + nh)*Ls + l] = s * invc;
    }
}

// ---------------- kernel 2: pairwise attention mix ----------------
__global__ void htatt_kernel(const int* __restrict__ hts)
{
    int bp = blockIdx.x;
    int b = bp / Pp;
    int he = hts[bp*2 + 0];
    int te = hts[bp*2 + 1];
    const float* ha = &g_e_att[((long)(b*NEe + he))*NHh*Ls];
    const float* ta = &g_e_att[((long)(b*NEe + te))*NHh*Ls];
    __shared__ float sv[Ls];
    __shared__ float red[256];
    float lsum = 0.f;
    for (int l = threadIdx.x; l < Ls; l += blockDim.x) {
        float s = 0.f;
        #pragma unroll
        for (int nh = 0; nh < NHh; nh++)
            s += ha[nh*Ls + l] * ta[nh*Ls + l];
        s *= (1.0f / NHh);
        sv[l] = s; lsum += s;
    }
    red[threadIdx.x] = lsum;
    for (int o = 128; o > 0; o >>= 1) {
        __syncthreads();
        if (threadIdx.x < o) red[threadIdx.x] += red[threadIdx.x + o];
    }
    __syncthreads();
    float inv = 1.0f / (red[0] + 1e-30f);
    for (int l = threadIdx.x; l < Ls; l += blockDim.x)
        g_ht[(long)bp*Ls + l] = sv[l] * inv;
}

// ---------------- 128x128 NN GEMM, 8x8 micro, double-buffered ----------------
// C = A @ B.  A [M,K] rm, B [K,N] rm. N%128==0, K%8==0. M clamped/masked.
__global__ __launch_bounds__(256,2) void gemm_nn128(
    const float* __restrict__ A, const float* __restrict__ B, float* __restrict__ C,
    int M, int N, int K, long sA, long sB, long sC)
{
    __shared__ float As[2][8][132];
    __shared__ float Bs[2][8][132];
    int bz = blockIdx.z;
    const float* Ab = A + (long)bz*sA;
    const float* Bp = B + (long)bz*sB;
    float*       Cb = C + (long)bz*sC;
    int m0 = blockIdx.x*128, n0 = blockIdx.y*128;
    int tid = threadIdx.x;

    int ar = tid >> 1, akq = (tid & 1)*4;        // A: row ar, k quad
    int am = m0 + ar; if (am > M-1) am = M-1;
    int bkr = tid >> 5, bnq = (tid & 31)*4;      // B: k row, n quad
    const float* aptr = Ab + (long)am*K + akq;
    const float* bptr = Bp + (long)bkr*N + n0 + bnq;

    float4 av = *(const float4*)aptr;
    float4 bv = *(const float4*)bptr;

    int tm = tid & 15, tn = tid >> 4;
    float acc[8][8] = {};
    int buf = 0;
    As[0][akq+0][ar] = av.x; As[0][akq+1][ar] = av.y;
    As[0][akq+2][ar] = av.z; As[0][akq+3][ar] = av.w;
    *(float4*)&Bs[0][bkr][bnq] = bv;
    __syncthreads();

    for (int k0 = 0; k0 < K; k0 += 8) {
        bool next = (k0 + 8 < K);
        if (next) {
            aptr += 8; bptr += (long)8*N;
            av = *(const float4*)aptr;
            bv = *(const float4*)bptr;
        }
        #pragma unroll
        for (int kk = 0; kk < 8; kk++) {
            float a[8], b[8];
            *(float4*)&a[0] = *(const float4*)&As[buf][kk][tm*8];
            *(float4*)&a[4] = *(const float4*)&As[buf][kk][tm*8+4];
            *(float4*)&b[0] = *(const float4*)&Bs[buf][kk][tn*8];
            *(float4*)&b[4] = *(const float4*)&Bs[buf][kk][tn*8+4];
            #pragma unroll
            for (int i = 0; i < 8; i++)
                #pragma unroll
                for (int j = 0; j < 8; j++)
                    acc[i][j] += a[i]*b[j];
        }
        if (next) {
            int nb = buf ^ 1;
            As[nb][akq+0][ar] = av.x; As[nb][akq+1][ar] = av.y;
            As[nb][akq+2][ar] = av.z; As[nb][akq+3][ar] = av.w;
            *(float4*)&Bs[nb][bkr][bnq] = bv;
            __syncthreads();
            buf = nb;
        }
    }
    #pragma unroll
    for (int i = 0; i < 8; i++) {
        int m = m0 + tm*8 + i;
        if (m >= M) continue;
        float4 o0 = make_float4(acc[i][0], acc[i][1], acc[i][2], acc[i][3]);
        float4 o1 = make_float4(acc[i][4], acc[i][5], acc[i][6], acc[i][7]);
        *(float4*)&Cb[(long)m*N + n0 + tn*8    ] = o0;
        *(float4*)&Cb[(long)m*N + n0 + tn*8 + 4] = o1;
    }
}

// ---------------- R GEMM (NT): g_R[side] = g_rs @ W[:, 768:]^T ----------------
// A = g_rs [BP,768]; W [768,1536] rm (use cols 768..1535). M=BP, N=768, K=768.
__global__ __launch_bounds__(256,2) void r_gemm(
    const float* __restrict__ headW, const float* __restrict__ tailW)
{
    __shared__ float As[2][8][132];
    __shared__ float Bs[2][8][132];
    int side = blockIdx.z;
    const float* W = side ? tailW : headW;
    float* Cb = g_R + (long)side*BP*Hh;
    int m0 = blockIdx.x*128, n0 = blockIdx.y*128;
    int tid = threadIdx.x;

    int ar = tid >> 1, akq = (tid & 1)*4;
    int am = m0 + ar; if (am > BP-1) am = BP-1;
    int bn = tid >> 1, bkq = (tid & 1)*4;
    const float* aptr = g_rs + (long)am*Hh + akq;
    const float* bptr = W + (long)(n0 + bn)*K2H + Hh + bkq;

    float4 av = *(const float4*)aptr;
    float4 bv = *(const float4*)bptr;

    int tm = tid & 15, tn = tid >> 4;
    float acc[8][8] = {};
    int buf = 0;
    As[0][akq+0][ar] = av.x; As[0][akq+1][ar] = av.y;
    As[0][akq+2][ar] = av.z; As[0][akq+3][ar] = av.w;
    Bs[0][bkq+0][bn] = bv.x; Bs[0][bkq+1][bn] = bv.y;
    Bs[0][bkq+2][bn] = bv.z; Bs[0][bkq+3][bn] = bv.w;
    __syncthreads();

    for (int k0 = 0; k0 < Hh; k0 += 8) {
        bool next = (k0 + 8 < Hh);
        if (next) {
            aptr += 8; bptr += 8;
            av = *(const float4*)aptr;
            bv = *(const float4*)bptr;
        }
        #pragma unroll
        for (int kk = 0; kk < 8; kk++) {
            float a[8], b[8];
            *(float4*)&a[0] = *(const float4*)&As[buf][kk][tm*8];
            *(float4*)&a[4] = *(const float4*)&As[buf][kk][tm*8+4];
            *(float4*)&b[0] = *(const float4*)&Bs[buf][kk][tn*8];
            *(float4*)&b[4] = *(const float4*)&Bs[buf][kk][tn*8+4];
            #pragma unroll
            for (int i = 0; i < 8; i++)
                #pragma unroll
                for (int j = 0; j < 8; j++)
                    acc[i][j] += a[i]*b[j];
        }
        if (next) {
            int nb = buf ^ 1;
            As[nb][akq+0][ar] = av.x; As[nb][akq+1][ar] = av.y;
            As[nb][akq+2][ar] = av.z; As[nb][akq+3][ar] = av.w;
            Bs[nb][bkq+0][bn] = bv.x; Bs[nb][bkq+1][bn] = bv.y;
            Bs[nb][bkq+2][bn] = bv.z; Bs[nb][bkq+3][bn] = bv.w;
            __syncthreads();
            buf = nb;
        }
    }
    #pragma unroll
    for (int i = 0; i < 8; i++) {
        int m = m0 + tm*8 + i;
        if (m >= BP) continue;
        float4 o0 = make_float4(acc[i][0], acc[i][1], acc[i][2], acc[i][3]);
        float4 o1 = make_float4(acc[i][4], acc[i][5], acc[i][6], acc[i][7]);
        *(float4*)&Cb[(long)m*Hh + n0 + tn*8    ] = o0;
        *(float4*)&Cb[(long)m*Hh + n0 + tn*8 + 4] = o1;
    }
}

// ---------------- E GEMM (NT, K-chunked, 64x64 tile): Ep = e_emb @ W1^T ------
// z = side + 2*kc.  K chunk = 256.  M=120 (clamped), N=768.
__global__ __launch_bounds__(256) void e_gemm(
    const float* __restrict__ headW, const float* __restrict__ tailW)
{
    __shared__ float As[16][65];
    __shared__ float Bs[16][65];
    int z = blockIdx.z;
    int side = z & 1, kc = z >> 1;
    const float* W = side ? tailW : headW;
    float* Cb = g_Ep + (long)(kc*2 + side)*BE*Hh;
    int m0 = blockIdx.x*64, n0 = blockIdx.y*64;
    int tid = threadIdx.x;
    int tm = tid & 15, tn = tid >> 4;
    float acc[4][4] = {};
    int kbeg = kc*256, kend = kbeg + 256;
    for (int k0 = kbeg; k0 < kend; k0 += 16) {
        #pragma unroll
        for (int i = 0; i < 4; i++) {
            int idx = tid + i*256;
            int m = idx >> 4, k = idx & 15;
            int mg = m0 + m; if (mg > BE-1) mg = BE-1;
            As[k][m] = g_e_emb[(long)mg*Hh + k0 + k];
        }
        #pragma unroll
        for (int i = 0; i < 4; i++) {
            int idx = tid + i*256;
            int e = idx >> 4, k = idx & 15;
            Bs[k][e] = W[(long)(n0 + e)*K2H + k0 + k];
        }
        __syncthreads();
        #pragma unroll
        for (int kk = 0; kk < 16; kk++) {
            float a[4], bb[4];
            #pragma unroll
            for (int i = 0; i < 4; i++) a[i]  = As[kk][tm + 16*i];
            #pragma unroll
            for (int j = 0; j < 4; j++) bb[j] = Bs[kk][tn + 16*j];
            #pragma unroll
            for (int i = 0; i < 4; i++)
                #pragma unroll
                for (int j = 0; j < 4; j++)
                    acc[i][j] += a[i]*bb[j];
        }
        __syncthreads();
    }
    #pragma unroll
    for (int i = 0; i < 4; i++) {
        int m = m0 + tm + 16*i;
        if (m >= BE) continue;
        #pragma unroll
        for (int j = 0; j < 4; j++)
            Cb[(long)m*Hh + n0 + tn + 16*j] = acc[i][j];
    }
}

// ---------------- fused gather + add + tanh ----------------
// hs/ts[m,e] = tanh( R[side][m,e] + sum_kc Ep[kc][side][ent][e] + bias[e] )
__global__ void fuse_tanh(const float* __restrict__ headb,
                          const float* __restrict__ tailb,
                          const int*   __restrict__ hts)
{
    int m = blockIdx.x, side = blockIdx.y;
    int b = m / Pp;
    int ent = hts[m*2 + side];
    int er = b*NEe + ent;
    const float* Rr   = g_R + ((long)side*BP + m)*Hh;
    const float* bias = side ? tailb : headb;
    float* outp = (side ? g_ts : g_hs) + (long)m*EMBe;
    const float* e0 = g_Ep + (long)(0*2 + side)*BE*Hh + (long)er*Hh;
    const float* e1 = g_Ep + (long)(1*2 + side)*BE*Hh + (long)er*Hh;
    const float* e2 = g_Ep + (long)(2*2 + side)*BE*Hh + (long)er*Hh;
    int e = threadIdx.x * 4;
    float4 r  = *(const float4*)&Rr[e];
    float4 p0 = *(const float4*)&e0[e];
    float4 p1 = *(const float4*)&e1[e];
    float4 p2 = *(const float4*)&e2[e];
    float4 bi = *(const float4*)&bias[e];
    float4 o;
    o.x = tanhf(r.x + p0.x + p1.x + p2.x + bi.x);
    o.y = tanhf(r.y + p0.y + p1.y + p2.y + bi.y);
    o.z = tanhf(r.z + p0.z + p1.z + p2.z + bi.z);
    o.w = tanhf(r.w + p0.w + p1.w + p2.w + bi.w);
    *(float4*)&outp[e] = o;
}

// ---------------- block-bilinear classifier (round-1 proven) -----------------
__global__ void bilinear_kernel(const float* __restrict__ clsb, float* __restrict__ out)
{
    __shared__ float hs_s[64][17];
    __shared__ float ts_s[64][17];
    __shared__ float Wc_s[256][33];
    int m0 = blockIdx.x*64;
    int c0 = blockIdx.y*32;
    int tid = threadIdx.x;
    int tm = tid & 15, tc = tid >> 4;
    float acc[4][2] = {};
    for (int kb = 0; kb < EMBe/16; kb++) {
        #pragma unroll
        for (int i = 0; i < 4; i++) {
            int idx = tid + i*256;
            int m = idx >> 4, k = idx & 15;
            float hv = 0.f, tv = 0.f;
            if (m0 + m < BP) {
                hv = g_hs[(long)(m0 + m)*EMBe + kb*16 + k];
                tv = g_ts[(long)(m0 + m)*EMBe + kb*16 + k];
            }
            hs_s[m][k] = hv; ts_s[m][k] = tv;
        }
        #pragma unroll
        for (int i = 0; i < 32; i++) {
            int idx = tid + i*256;
            int c = idx >> 8, q = idx & 255;
            float w = 0.f;
            if (c0 + c < NCc) w = g_Wc[(long)(c0 + c)*QQ + kb*256 + q];
            Wc_s[q][c] = w;
        }
        __syncthreads();
        #pragma unroll 1
        for (int i = 0; i < 16; i++) {
            float a[4];
            #pragma unroll
            for (int im = 0; im < 4; im++) a[im] = hs_s[tm + 16*im][i];
            #pragma unroll
            for (int j = 0; j < 16; j++) {
                float w0 = Wc_s[i*16 + j][tc];
                float w1 = Wc_s[i*16 + j][tc + 16];
                #pragma unroll
                for (int im = 0; im < 4; im++) {
                    float pv = a[im] * ts_s[tm + 16*im][j];
                    acc[im][0] += pv * w0;
                    acc[im][1] += pv * w1;
                }
            }
        }
        __syncthreads();
    }
    #pragma unroll
    for (int im = 0; im < 4; im++) {
        int m = m0 + tm + 16*im;
        if (m >= BP) continue;
        #pragma unroll
        for (int jc = 0; jc < 2; jc++) {
            int c = c0 + tc + 16*jc;
            if (c < NCc) out[(long)m*NCc + c] = acc[im][jc] + clsb[c];
        }
    }
}

// ---------------- launch ----------------
extern "C" void kernel_launch(void* const* d_in, const int* in_sizes, int n_in,
                              void* d_out, int out_size)
{
    const float* seq   = (const float*)d_in[0];
    const float* att   = (const float*)d_in[1];
    const float* headW = (const float*)d_in[2];
    const float* headb = (const float*)d_in[3];
    const float* tailW = (const float*)d_in[4];
    const float* tailb = (const float*)d_in[5];
    const float* projW = (const float*)d_in[6];
    const float* clsW  = (const float*)d_in[7];
    const float* clsb  = (const float*)d_in[8];
    const float* mmask = (const float*)d_in[9];
    const int*   midx  = (const int*)d_in[10];
    const int*   hts   = (const int*)d_in[11];
    float* out = (float*)d_out;

    float *p_ht, *p_rs, *p_Wc;
    cudaGetSymbolAddress((void**)&p_ht, g_ht);
    cudaGetSymbolAddress((void**)&p_rs, g_rs);
    cudaGetSymbolAddress((void**)&p_Wc, g_Wc);

    // Wc = cls_W @ proj_W   [97,768]@[768,12288]
    {
        dim3 g(1, QQ/128, 1);
        gemm_nn128<<<g, 256>>>(clsW, projW, p_Wc, NCc, QQ, Hh, 0, 0, 0);
    }
    pool_kernel<<<Bb*NEe, 256>>>(seq, att, mmask, midx);
    htatt_kernel<<<Bb*Pp, 256>>>(hts);
    // E partials: e_emb @ W1^T (first half of head/tail W)
    {
        dim3 g(2, Hh/64, 2*EKC);
        e_gemm<<<g, 256>>>(headW, tailW);
    }
    // rs[b] = ht[b] @ seq[b]  (600x1024)@(1024x768)
    {
        dim3 g((Pp + 127)/128, Hh/128, Bb);
        gemm_nn128<<<g, 256>>>(p_ht, seq, p_rs, Pp, Hh, Ls,
                               (long)Pp*Ls, (long)Ls*Hh, (long)Pp*Hh);
    }
    // R[side] = rs @ W2^T
    {
        dim3 g((BP + 127)/128, Hh/128, 2);
        r_gemm<<<g, 256>>>(headW, tailW);
    }
    // hs/ts = tanh(R + E[ent] + b)
    {
        dim3 g(BP, 2);
        fuse_tanh<<<g, 192>>>(headb, tailb, hts);
    }
    // classifier
    {
        dim3 g((BP + 63)/64, (NCc + 31)/32, 1);
        bilinear_kernel<<<g, 256>>>(clsb, out);
    }
}